// round 14
// baseline (speedup 1.0000x reference)
#include <cuda_runtime.h>
#include <cuda_bf16.h>
#include <stdint.h>

#define N_NODES 50000
#define N_EDGES 600000
#define IN_DIM 128
#define HID 256
#define N_CLASSES 16

#define SCAN_BLOCK 256
#define N_SBLOCKS ((N_NODES + SCAN_BLOCK - 1) / SCAN_BLOCK)   // 196

// ---------------- device scratch (no allocation allowed) ----------------
__device__ int   g_cnt[N_NODES];
__device__ int   g_blockoff[N_SBLOCKS];
__device__ int   g_rowptr[N_NODES + 1];
__device__ int   g_cursor[N_NODES];
__device__ int   g_col[N_EDGES];
__device__ float g_agg[(size_t)N_NODES * HID];
__device__ float g_h1[(size_t)N_NODES * HID];
__device__ float g_h2[(size_t)N_NODES * HID];
__device__ __nv_bfloat16 g_xb[(size_t)N_NODES * IN_DIM];   // x in bf16 (gather operand)
__device__ __nv_bfloat16 g_h1b[(size_t)N_NODES * HID];     // h1 in bf16 (gather operand)
__device__ float g_w1t[2 * IN_DIM * HID];                  // [w1_l ; w1_r] tf32
__device__ float g_w2t[2 * HID * HID];                     // [w2_l ; w2_r] tf32

// ---------------- helpers ----------------
__device__ __forceinline__ float to_tf32(float x) {
    uint32_t u;
    asm("cvt.rna.tf32.f32 %0, %1;" : "=r"(u) : "f"(x));
    return __uint_as_float(u);
}

__device__ __forceinline__ void mma_tf32(float* d, const uint32_t* a, uint32_t b0, uint32_t b1) {
    asm volatile(
        "mma.sync.aligned.m16n8k8.row.col.f32.tf32.tf32.f32 "
        "{%0,%1,%2,%3}, {%4,%5,%6,%7}, {%8,%9}, {%0,%1,%2,%3};"
        : "+f"(d[0]), "+f"(d[1]), "+f"(d[2]), "+f"(d[3])
        : "r"(a[0]), "r"(a[1]), "r"(a[2]), "r"(a[3]), "r"(b0), "r"(b1));
}

__device__ __forceinline__ void acc_bf16x4(float* acc, uint2 q) {
    float2 f0 = __bfloat1622float2(*reinterpret_cast<__nv_bfloat162*>(&q.x));
    float2 f1 = __bfloat1622float2(*reinterpret_cast<__nv_bfloat162*>(&q.y));
    acc[0] += f0.x; acc[1] += f0.y; acc[2] += f1.x; acc[3] += f1.y;
}
__device__ __forceinline__ void acc_bf16x8(float* acc, uint4 q) {
    float2 f0 = __bfloat1622float2(*reinterpret_cast<__nv_bfloat162*>(&q.x));
    float2 f1 = __bfloat1622float2(*reinterpret_cast<__nv_bfloat162*>(&q.y));
    float2 f2 = __bfloat1622float2(*reinterpret_cast<__nv_bfloat162*>(&q.z));
    float2 f3 = __bfloat1622float2(*reinterpret_cast<__nv_bfloat162*>(&q.w));
    acc[0] += f0.x; acc[1] += f0.y; acc[2] += f1.x; acc[3] += f1.y;
    acc[4] += f2.x; acc[5] += f2.y; acc[6] += f3.x; acc[7] += f3.y;
}

// ---------------- prep: zero cnt + weight tf32 cvts ----------------
__global__ void prep_k(const float* __restrict__ w1_l, const float* __restrict__ w1_r,
                       const float* __restrict__ w2_l, const float* __restrict__ w2_r) {
    int i = blockIdx.x * blockDim.x + threadIdx.x;
    if (i < N_NODES) g_cnt[i] = 0;
    const int H1 = IN_DIM * HID;
    if (i < 2 * H1)
        g_w1t[i] = to_tf32(i < H1 ? w1_l[i] : w1_r[i - H1]);
    const int H2 = HID * HID;
    if (i < 2 * H2)
        g_w2t[i] = to_tf32(i < H2 ? w2_l[i] : w2_r[i - H2]);
}

// ---------------- x -> bf16 ----------------
__global__ void cvt_xb(const float* __restrict__ x) {
    int i = blockIdx.x * blockDim.x + threadIdx.x;     // pair index
    const int NP = N_NODES * IN_DIM / 2;
    if (i >= NP) return;
    float2 v = reinterpret_cast<const float2*>(x)[i];
    reinterpret_cast<__nv_bfloat162*>(g_xb)[i] = __float22bfloat162_rn(v);
}

// ---------------- CSR build ----------------
__global__ void hist_kernel(const int* __restrict__ ei) {
    int e = blockIdx.x * blockDim.x + threadIdx.x;
    if (e >= N_EDGES) return;
    int d = min(max(ei[N_EDGES + e], 0), N_NODES - 1);
    atomicAdd(&g_cnt[d], 1);
}
__global__ void block_reduce_k() {
    __shared__ int sm[SCAN_BLOCK];
    int i = blockIdx.x * SCAN_BLOCK + threadIdx.x;
    sm[threadIdx.x] = (i < N_NODES) ? g_cnt[i] : 0;
    __syncthreads();
#pragma unroll
    for (int o = SCAN_BLOCK / 2; o > 0; o >>= 1) {
        if (threadIdx.x < o) sm[threadIdx.x] += sm[threadIdx.x + o];
        __syncthreads();
    }
    if (threadIdx.x == 0) g_blockoff[blockIdx.x] = sm[0];
}
__global__ void scan_blocksums_k() {
    __shared__ int sm[256];
    int t = threadIdx.x;
    int v = (t < N_SBLOCKS) ? g_blockoff[t] : 0;
    sm[t] = v;
    __syncthreads();
#pragma unroll
    for (int o = 1; o < 256; o <<= 1) {
        int u = (t >= o) ? sm[t - o] : 0;
        __syncthreads();
        sm[t] += u;
        __syncthreads();
    }
    if (t < N_SBLOCKS) g_blockoff[t] = sm[t] - v;
}
__global__ void block_scan_k() {
    __shared__ int sm[SCAN_BLOCK];
    int i = blockIdx.x * SCAN_BLOCK + threadIdx.x;
    int v = (i < N_NODES) ? g_cnt[i] : 0;
    sm[threadIdx.x] = v;
    __syncthreads();
#pragma unroll
    for (int o = 1; o < SCAN_BLOCK; o <<= 1) {
        int u = (threadIdx.x >= o) ? sm[threadIdx.x - o] : 0;
        __syncthreads();
        sm[threadIdx.x] += u;
        __syncthreads();
    }
    if (i < N_NODES) {
        int excl = sm[threadIdx.x] - v + g_blockoff[blockIdx.x];
        g_rowptr[i] = excl;
        g_cursor[i] = excl;
    }
    if (i == 0) g_rowptr[N_NODES] = N_EDGES;
}
__global__ void fill_kernel(const int* __restrict__ ei) {
    int e = blockIdx.x * blockDim.x + threadIdx.x;
    if (e >= N_EDGES) return;
    int s = min(max(ei[e], 0), N_NODES - 1);
    int d = min(max(ei[N_EDGES + e], 0), N_NODES - 1);
    int pos = atomicAdd(&g_cursor[d], 1);
    g_col[pos] = s;
}

// ---------------- gather mean layer1 (bf16 x), warp per node ----------------
// row = 128 bf16 = 32 lanes x uint2 (4 bf16)
__global__ void gather_mean_128() {
    int w = (blockIdx.x * blockDim.x + threadIdx.x) >> 5;
    int lane = threadIdx.x & 31;
    if (w >= N_NODES) return;
    int beg = g_rowptr[w], end = g_rowptr[w + 1];
    const uint2* xv = reinterpret_cast<const uint2*>(g_xb);
    float acc[4] = {0.f, 0.f, 0.f, 0.f};
    int j = beg;
    for (; j + 4 <= end; j += 4) {
        int s0 = __ldg(&g_col[j + 0]);
        int s1 = __ldg(&g_col[j + 1]);
        int s2 = __ldg(&g_col[j + 2]);
        int s3 = __ldg(&g_col[j + 3]);
        uint2 q0 = __ldg(xv + (size_t)s0 * 32 + lane);
        uint2 q1 = __ldg(xv + (size_t)s1 * 32 + lane);
        uint2 q2 = __ldg(xv + (size_t)s2 * 32 + lane);
        uint2 q3 = __ldg(xv + (size_t)s3 * 32 + lane);
        acc_bf16x4(acc, q0); acc_bf16x4(acc, q1);
        acc_bf16x4(acc, q2); acc_bf16x4(acc, q3);
    }
    for (; j < end; j++) {
        int s = __ldg(&g_col[j]);
        acc_bf16x4(acc, __ldg(xv + (size_t)s * 32 + lane));
    }
    float inv = 1.0f / (float)max(end - beg, 1);
    float4 o;
    o.x = to_tf32(acc[0] * inv); o.y = to_tf32(acc[1] * inv);
    o.z = to_tf32(acc[2] * inv); o.w = to_tf32(acc[3] * inv);
    reinterpret_cast<float4*>(g_agg + (size_t)w * IN_DIM)[lane] = o;
}

// ---------------- gather mean layer2 (bf16 h1), warp per node ----------------
// row = 256 bf16 = 32 lanes x uint4 (8 bf16)
__global__ void gather_mean_256() {
    int w = (blockIdx.x * blockDim.x + threadIdx.x) >> 5;
    int lane = threadIdx.x & 31;
    if (w >= N_NODES) return;
    int beg = g_rowptr[w], end = g_rowptr[w + 1];
    const uint4* hv = reinterpret_cast<const uint4*>(g_h1b);
    float acc[8] = {0.f, 0.f, 0.f, 0.f, 0.f, 0.f, 0.f, 0.f};
    int j = beg;
    for (; j + 4 <= end; j += 4) {
        int s0 = __ldg(&g_col[j + 0]);
        int s1 = __ldg(&g_col[j + 1]);
        int s2 = __ldg(&g_col[j + 2]);
        int s3 = __ldg(&g_col[j + 3]);
        uint4 q0 = __ldg(hv + (size_t)s0 * 32 + lane);
        uint4 q1 = __ldg(hv + (size_t)s1 * 32 + lane);
        uint4 q2 = __ldg(hv + (size_t)s2 * 32 + lane);
        uint4 q3 = __ldg(hv + (size_t)s3 * 32 + lane);
        acc_bf16x8(acc, q0); acc_bf16x8(acc, q1);
        acc_bf16x8(acc, q2); acc_bf16x8(acc, q3);
    }
    for (; j < end; j++) {
        int s = __ldg(&g_col[j]);
        acc_bf16x8(acc, __ldg(hv + (size_t)s * 32 + lane));
    }
    float inv = 1.0f / (float)max(end - beg, 1);
    float* dst = g_agg + (size_t)w * HID + lane * 8;
    float4 o0, o1;
    o0.x = to_tf32(acc[0] * inv); o0.y = to_tf32(acc[1] * inv);
    o0.z = to_tf32(acc[2] * inv); o0.w = to_tf32(acc[3] * inv);
    o1.x = to_tf32(acc[4] * inv); o1.y = to_tf32(acc[5] * inv);
    o1.z = to_tf32(acc[6] * inv); o1.w = to_tf32(acc[7] * inv);
    reinterpret_cast<float4*>(dst)[0] = o0;
    reinterpret_cast<float4*>(dst)[1] = o1;
}

// ---------------- tf32 tensor-core SAGE GEMM, BM=128 BN=256 BK=32, 512 thr ----------------
#define AS_STRIDE 36
#define BS_STRIDE 264
#define AS_BUF (128 * AS_STRIDE)
#define BS_BUF (32 * BS_STRIDE)

// EMIT_BF16: also write C as bf16 into g_h1b (layer-1 only)
template <int KHALF, bool CVT_A, bool CVT_OUT, bool EMIT_BF16>
__global__ void __launch_bounds__(512, 1)
sage_tf32(const float* __restrict__ A0, const float* __restrict__ A1,
          const float* __restrict__ W, const float* __restrict__ bias,
          float* __restrict__ C) {
    extern __shared__ float smem[];
    float* As = smem;
    float* Bs = smem + 2 * AS_BUF;

    const int tid = threadIdx.x;
    const int lane = tid & 31;
    const int wid = tid >> 5;
    const int wm = wid & 3;
    const int wn = wid >> 2;
    const int rowBase = blockIdx.x * 128;
    const int NT = (2 * KHALF) / 32;

    float acc[2][8][4];
#pragma unroll
    for (int i = 0; i < 2; i++)
#pragma unroll
        for (int j = 0; j < 8; j++)
#pragma unroll
            for (int k = 0; k < 4; k++) acc[i][j][k] = 0.0f;

    auto issue = [&](int buf, int k0) {
        float* Asb = As + buf * AS_BUF;
        float* Bsb = Bs + buf * BS_BUF;
        const float* Abase = (k0 < KHALF) ? A0 : A1;
        int kb = (k0 < KHALF) ? k0 : (k0 - KHALF);
#pragma unroll
        for (int i = 0; i < 2; i++) {
            int idx = tid + 512 * i;
            int r = idx >> 3, kc = idx & 7;
            int row = rowBase + r;
            const float* src = Abase + (size_t)row * KHALF + kb + kc * 4;
            uint32_t dst = (uint32_t)__cvta_generic_to_shared(Asb + r * AS_STRIDE + kc * 4);
            int sz = (row < N_NODES) ? 16 : 0;
            asm volatile("cp.async.ca.shared.global [%0], [%1], 16, %2;"
                         :: "r"(dst), "l"(src), "r"(sz));
        }
#pragma unroll
        for (int i = 0; i < 4; i++) {
            int idx = tid + 512 * i;
            int k = idx >> 6, c4 = idx & 63;
            const float* src = W + (size_t)(k0 + k) * HID + c4 * 4;
            uint32_t dst = (uint32_t)__cvta_generic_to_shared(Bsb + k * BS_STRIDE + c4 * 4);
            asm volatile("cp.async.ca.shared.global [%0], [%1], 16;"
                         :: "r"(dst), "l"(src));
        }
        asm volatile("cp.async.commit_group;");
    };

    issue(0, 0);
    for (int t = 0; t < NT; t++) {
        if (t + 1 < NT) {
            issue((t + 1) & 1, (t + 1) * 32);
            asm volatile("cp.async.wait_group 1;");
        } else {
            asm volatile("cp.async.wait_group 0;");
        }
        __syncthreads();
        const float* Asb = As + (t & 1) * AS_BUF;
        const float* Bsb = Bs + (t & 1) * BS_BUF;
#pragma unroll
        for (int k8 = 0; k8 < 4; k8++) {
            int kb = k8 * 8;
            uint32_t a[2][4];
#pragma unroll
            for (int mt = 0; mt < 2; mt++) {
                int m = wm * 32 + mt * 16 + (lane >> 2);
                int k = kb + (lane & 3);
                float a0 = Asb[m * AS_STRIDE + k];
                float a1 = Asb[(m + 8) * AS_STRIDE + k];
                float a2 = Asb[m * AS_STRIDE + k + 4];
                float a3 = Asb[(m + 8) * AS_STRIDE + k + 4];
                if (CVT_A) { a0 = to_tf32(a0); a1 = to_tf32(a1); a2 = to_tf32(a2); a3 = to_tf32(a3); }
                a[mt][0] = __float_as_uint(a0);
                a[mt][1] = __float_as_uint(a1);
                a[mt][2] = __float_as_uint(a2);
                a[mt][3] = __float_as_uint(a3);
            }
#pragma unroll
            for (int nt = 0; nt < 8; nt++) {
                int n = wn * 64 + nt * 8 + (lane >> 2);
                int k = kb + (lane & 3);
                uint32_t b0 = __float_as_uint(Bsb[k * BS_STRIDE + n]);
                uint32_t b1 = __float_as_uint(Bsb[(k + 4) * BS_STRIDE + n]);
                mma_tf32(acc[0][nt], a[0], b0, b1);
                mma_tf32(acc[1][nt], a[1], b0, b1);
            }
        }
        __syncthreads();
    }

#pragma unroll
    for (int mt = 0; mt < 2; mt++) {
        int r0 = rowBase + wm * 32 + mt * 16 + (lane >> 2);
#pragma unroll
        for (int nt = 0; nt < 8; nt++) {
            int c = wn * 64 + nt * 8 + (lane & 3) * 2;
            float bv0 = __ldg(bias + c);
            float bv1 = __ldg(bias + c + 1);
            float v0 = fmaxf(acc[mt][nt][0] + bv0, 0.0f);
            float v1 = fmaxf(acc[mt][nt][1] + bv1, 0.0f);
            float v2 = fmaxf(acc[mt][nt][2] + bv0, 0.0f);
            float v3 = fmaxf(acc[mt][nt][3] + bv1, 0.0f);
            if (CVT_OUT) {
                v0 = to_tf32(v0); v1 = to_tf32(v1);
                v2 = to_tf32(v2); v3 = to_tf32(v3);
            }
            if (r0 < N_NODES) {
                *reinterpret_cast<float2*>(C + (size_t)r0 * HID + c) = make_float2(v0, v1);
                if (EMIT_BF16)
                    *reinterpret_cast<__nv_bfloat162*>(g_h1b + (size_t)r0 * HID + c) =
                        __float22bfloat162_rn(make_float2(v0, v1));
            }
            if (r0 + 8 < N_NODES) {
                *reinterpret_cast<float2*>(C + (size_t)(r0 + 8) * HID + c) = make_float2(v2, v3);
                if (EMIT_BF16)
                    *reinterpret_cast<__nv_bfloat162*>(g_h1b + (size_t)(r0 + 8) * HID + c) =
                        __float22bfloat162_rn(make_float2(v2, v3));
            }
        }
    }
}

// ---------------- classifier ----------------
__global__ void classifier_k(const float* __restrict__ wc,
                             const float* __restrict__ bc,
                             float* __restrict__ out) {
    __shared__ float w[HID * N_CLASSES];
    __shared__ float hrow[8][HID];
    for (int i = threadIdx.x; i < HID * N_CLASSES; i += blockDim.x)
        w[i] = wc[i];
    __syncthreads();

    int warp = threadIdx.x >> 5;
    int lane = threadIdx.x & 31;
    int row = blockIdx.x * 8 + warp;
    if (row >= N_NODES) return;

    const float* h = g_h2 + (size_t)row * HID;
    for (int k = lane; k < HID; k += 32) hrow[warp][k] = h[k];
    __syncwarp();

    int c = lane & 15;
    int p = lane >> 4;
    float acc = 0.0f;
    int kbeg = p * (HID / 2);
#pragma unroll 8
    for (int k = kbeg; k < kbeg + HID / 2; k++)
        acc += hrow[warp][k] * w[k * N_CLASSES + c];
    acc += __shfl_xor_sync(0xffffffffu, acc, 16);
    if (lane < 16) out[(size_t)row * N_CLASSES + lane] = acc + bc[lane];
}

// ---------------- launch ----------------
extern "C" void kernel_launch(void* const* d_in, const int* in_sizes, int n_in,
                              void* d_out, int out_size) {
    const float* x    = (const float*)d_in[0];
    const int*   ei   = (const int*)d_in[1];
    const float* w1_l = (const float*)d_in[2];
    const float* b1_l = (const float*)d_in[3];
    const float* w1_r = (const float*)d_in[4];
    const float* w2_l = (const float*)d_in[5];
    const float* b2_l = (const float*)d_in[6];
    const float* w2_r = (const float*)d_in[7];
    const float* wc   = (const float*)d_in[8];
    const float* bc   = (const float*)d_in[9];
    float* out = (float*)d_out;

    // resolve REAL device addresses (GB300 ATS pitfall: never pass symbols as args)
    void *p_agg, *p_h1, *p_h2, *p_w1t, *p_w2t;
    cudaGetSymbolAddress(&p_agg, g_agg);
    cudaGetSymbolAddress(&p_h1,  g_h1);
    cudaGetSymbolAddress(&p_h2,  g_h2);
    cudaGetSymbolAddress(&p_w1t, g_w1t);
    cudaGetSymbolAddress(&p_w2t, g_w2t);

    const int SMEM = (2 * AS_BUF + 2 * BS_BUF) * 4;   // 104448 B
    cudaFuncSetAttribute(sage_tf32<IN_DIM, true, true, true>,
                         cudaFuncAttributeMaxDynamicSharedMemorySize, SMEM);
    cudaFuncSetAttribute(sage_tf32<HID, false, false, false>,
                         cudaFuncAttributeMaxDynamicSharedMemorySize, SMEM);

    // ---- prep ----
    prep_k<<<(2 * HID * HID + 255) / 256, 256>>>(w1_l, w1_r, w2_l, w2_r);
    cvt_xb<<<(N_NODES * IN_DIM / 2 + 255) / 256, 256>>>(x);

    // ---- CSR build ----
    hist_kernel<<<(N_EDGES + 255) / 256, 256>>>(ei);
    block_reduce_k<<<N_SBLOCKS, SCAN_BLOCK>>>();
    scan_blocksums_k<<<1, 256>>>();
    block_scan_k<<<N_SBLOCKS, SCAN_BLOCK>>>();
    fill_kernel<<<(N_EDGES + 255) / 256, 256>>>(ei);

    // ---- layer 1 ----
    gather_mean_128<<<(N_NODES * 32 + 255) / 256, 256>>>();
    {
        dim3 grid((N_NODES + 127) / 128, 1);
        sage_tf32<IN_DIM, true, true, true><<<grid, 512, SMEM>>>(
            (const float*)p_agg, x, (const float*)p_w1t, b1_l, (float*)p_h1);
    }

    // ---- layer 2 ----
    gather_mean_256<<<(N_NODES * 32 + 255) / 256, 256>>>();
    {
        dim3 grid((N_NODES + 127) / 128, 1);
        sage_tf32<HID, false, false, false><<<grid, 512, SMEM>>>(
            (const float*)p_agg, (const float*)p_h1, (const float*)p_w2t, b2_l, (float*)p_h2);
    }

    // ---- classifier ----
    classifier_k<<<(N_NODES + 7) / 8, 256>>>(wc, bc, out);
}